// round 6
// baseline (speedup 1.0000x reference)
#include <cuda_runtime.h>
#include <cuda_bf16.h>
#include <cstdint>
#include <cstddef>

#define NQ   65536
#define MS   65536
#define HN   32
#define CIN  64
#define CO   64
#define KP   15
#define KTOT 960            // KP * CIN

// ---- device scratch ----------------------------------------------------------
__device__ __nv_bfloat16 g_wth[(size_t)NQ * KTOT];   // weighted, bf16 hi
__device__ __nv_bfloat16 g_wtl[(size_t)NQ * KTOT];   // weighted, bf16 lo
__device__ __nv_bfloat16 g_Wth[(size_t)CO * KTOT];   // W^T [o][k*64+i], bf16 hi
__device__ __nv_bfloat16 g_Wtl[(size_t)CO * KTOT];   // W^T, bf16 lo
__device__ __nv_bfloat16 g_xh[(size_t)MS * CIN];     // x, bf16 hi
__device__ __nv_bfloat16 g_xl[(size_t)MS * CIN];     // x, bf16 lo

__device__ float g_sums[CO];
__device__ float g_sumsq[CO];
__device__ float g_scale[CO];
__device__ float g_bias[CO];

// ---- helpers -------------------------------------------------------------------
static __device__ __forceinline__ float fast_sqrt(float x) {
    float r;
    asm("sqrt.approx.f32 %0, %1;" : "=f"(r) : "f"(x));
    return r;
}
static __device__ __forceinline__ void cp_async16(uint32_t smem_dst, const void* gmem_src) {
    asm volatile("cp.async.cg.shared.global [%0], [%1], 16;"
                 :: "r"(smem_dst), "l"(gmem_src));
}
static __device__ __forceinline__ void cp_commit() { asm volatile("cp.async.commit_group;"); }
static __device__ __forceinline__ void cp_wait0()  { asm volatile("cp.async.wait_group 0;"); }
static __device__ __forceinline__ void cp_wait1()  { asm volatile("cp.async.wait_group 1;"); }

static __device__ __forceinline__ uint32_t smem_u32(const void* p) {
    uint32_t a;
    asm("{ .reg .u64 t; cvta.to.shared.u64 t, %1; cvt.u32.u64 %0, t; }" : "=r"(a) : "l"(p));
    return a;
}

#define SWZ128(b)   ((b) ^ (((b) >> 3) & 0x70))

#define LDSM4(r0, r1, r2, r3, addr) \
    asm volatile("ldmatrix.sync.aligned.m8n8.x4.shared.b16 {%0,%1,%2,%3}, [%4];" \
        : "=r"(r0), "=r"(r1), "=r"(r2), "=r"(r3) : "r"(addr))

#define LDSM4T(r0, r1, r2, r3, addr) \
    asm volatile("ldmatrix.sync.aligned.m8n8.x4.trans.shared.b16 {%0,%1,%2,%3}, [%4];" \
        : "=r"(r0), "=r"(r1), "=r"(r2), "=r"(r3) : "r"(addr))

#define MMA16816(c, a0, a1, a2, a3, b0, b1) \
    asm volatile("mma.sync.aligned.m16n8k16.row.col.f32.bf16.bf16.f32 " \
        "{%0,%1,%2,%3}, {%4,%5,%6,%7}, {%8,%9}, {%0,%1,%2,%3};" \
        : "+f"((c)[0]), "+f"((c)[1]), "+f"((c)[2]), "+f"((c)[3]) \
        : "r"(a0), "r"(a1), "r"(a2), "r"(a3), "r"(b0), "r"(b1))

// =============================================================================
// Kernel P1: split x -> bf16 hi/lo
// =============================================================================
__global__ void __launch_bounds__(256)
prep_x(const float* __restrict__ x) {
    const int i = blockIdx.x * 256 + threadIdx.x;
    float v = x[i];
    __nv_bfloat16 hi = __float2bfloat16(v);
    __nv_bfloat16 lo = __float2bfloat16(v - __bfloat162float(hi));
    g_xh[i] = hi;
    g_xl[i] = lo;
}

// =============================================================================
// Kernel P2: split/transpose W -> Wt[o][k*64+i] bf16 hi/lo
// =============================================================================
__global__ void __launch_bounds__(64)
prep_w(const float* __restrict__ Wg) {
    const int ki = blockIdx.x;              // 0..959
    const int o  = threadIdx.x;             // 0..63
    float w = Wg[ki * 64 + o];
    __nv_bfloat16 hi = __float2bfloat16(w);
    __nv_bfloat16 lo = __float2bfloat16(w - __bfloat162float(hi));
    g_Wth[(size_t)o * KTOT + ki] = hi;
    g_Wtl[(size_t)o * KTOT + ki] = lo;
}

// =============================================================================
// Kernel A: HMMA aggregation. Warp per query:
//   weighted[16(pad), 64] = infl[16, 32] x gathered_x[32, 64]   (3-term bf16)
// Per-warp SMEM: x_hi 4KB (SW128), x_lo 4KB, infl_hi 1280B (80B rows), infl_lo 1280B
// =============================================================================
#define AW_STRIDE 10752
#define AW_XH 0
#define AW_XL 4096
#define AW_IH 8192
#define AW_IL 9472

__global__ void __launch_bounds__(128)
kpconv_aggregate_tc(const float* __restrict__ q_pts,
                    const float* __restrict__ s_pts,
                    const int*   __restrict__ nbr,
                    const float* __restrict__ kp)
{
    __shared__ char smA[4 * AW_STRIDE];
    __shared__ float4 kp4s[16];

    const uint32_t sbA = smem_u32(smA);
    const int tid  = threadIdx.x;
    const int warp = tid >> 5;
    const int lane = tid & 31;

    if (blockIdx.x == 0 && tid < CO) { g_sums[tid] = 0.f; g_sumsq[tid] = 0.f; }

    if (tid < 16) {
        float4 v = make_float4(0.f, 0.f, 0.f, 0.f);
        if (tid < KP) {
            v.x = kp[tid * 3 + 0];
            v.y = kp[tid * 3 + 1];
            v.z = kp[tid * 3 + 2];
        }
        kp4s[tid] = v;
    }
    __syncthreads();

    const double EXT_D = 0.1 * 1.2 / 2.5;
    const float  INV_E = (float)(1.0 / EXT_D);

    const int q = blockIdx.x * 4 + warp;
    const uint32_t wb = sbA + warp * AW_STRIDE;

    // ---- influence (lane = neighbor) ----
    const float qx = q_pts[q * 3 + 0];
    const float qy = q_pts[q * 3 + 1];
    const float qz = q_pts[q * 3 + 2];

    const int idx = nbr[q * HN + lane];
    const float rx = s_pts[idx * 3 + 0] - qx;
    const float ry = s_pts[idx * 3 + 1] - qy;
    const float rz = s_pts[idx * 3 + 2] - qz;

    #pragma unroll
    for (int k = 0; k < 16; ++k) {
        float w = 0.f;
        if (k < KP) {
            float4 kv = kp4s[k];
            float dx = rx - kv.x, dy = ry - kv.y, dz = rz - kv.z;
            float d2 = fmaf(dx, dx, fmaf(dy, dy, dz * dz));
            float s  = fast_sqrt(d2);
            w = fmaxf(fmaf(s, -INV_E, 1.f), 0.f);
        }
        __nv_bfloat16 h = __float2bfloat16(w);
        __nv_bfloat16 l = __float2bfloat16(w - __bfloat162float(h));
        // infl[k][h=lane], 80B row stride (conflict-free ldmatrix)
        *(__nv_bfloat16*)(smA + warp * AW_STRIDE + AW_IH + k * 80 + lane * 2) = h;
        *(__nv_bfloat16*)(smA + warp * AW_STRIDE + AW_IL + k * 80 + lane * 2) = l;
    }

    // ---- gather x rows (SW128 layout, 128B rows) ----
    #pragma unroll
    for (int i = 0; i < 8; ++i) {
        const int v = i * 32 + lane;
        const int r = v >> 3, u = v & 7;
        const int ir = __shfl_sync(0xffffffffu, idx, r);
        const uint32_t d = SWZ128((uint32_t)(r * 128 + u * 16));
        cp_async16(wb + AW_XH + d, g_xh + (size_t)ir * CIN + u * 8);
        cp_async16(wb + AW_XL + d, g_xl + (size_t)ir * CIN + u * 8);
    }
    cp_commit();
    cp_wait0();
    __syncthreads();

    // ---- MMAs ----
    float acc[8][4];
    #pragma unroll
    for (int t = 0; t < 8; ++t)
        #pragma unroll
        for (int e = 0; e < 4; ++e) acc[t][e] = 0.f;

    const int krow_base = (lane & 7) + ((lane >> 3) & 1) * 8;
    const uint32_t a_off = (uint32_t)((lane & 15) * 80 + (lane >> 4) * 16);

    #pragma unroll
    for (int s = 0; s < 2; ++s) {
        uint32_t ah0, ah1, ah2, ah3, al0, al1, al2, al3;
        LDSM4(ah0, ah1, ah2, ah3, wb + AW_IH + a_off + s * 32);
        LDSM4(al0, al1, al2, al3, wb + AW_IL + a_off + s * 32);

        const int krow = s * 16 + krow_base;
        #pragma unroll
        for (int t = 0; t < 4; ++t) {
            const uint32_t boff = SWZ128((uint32_t)(krow * 128 + t * 32 + ((lane >> 4) * 16)));
            uint32_t bh0, bh1, bh2, bh3, bl0, bl1, bl2, bl3;
            LDSM4T(bh0, bh1, bh2, bh3, wb + AW_XH + boff);
            LDSM4T(bl0, bl1, bl2, bl3, wb + AW_XL + boff);

            MMA16816(acc[2 * t],     ah0, ah1, ah2, ah3, bh0, bh1);
            MMA16816(acc[2 * t],     ah0, ah1, ah2, ah3, bl0, bl1);
            MMA16816(acc[2 * t],     al0, al1, al2, al3, bh0, bh1);
            MMA16816(acc[2 * t + 1], ah0, ah1, ah2, ah3, bh2, bh3);
            MMA16816(acc[2 * t + 1], ah0, ah1, ah2, ah3, bl2, bl3);
            MMA16816(acc[2 * t + 1], al0, al1, al2, al3, bh2, bh3);
        }
    }

    // ---- epilogue: split weighted -> bf16 hi/lo, write ----
    const int kp0 = lane >> 2;            // 0..7
    const int kp1 = kp0 + 8;              // 8..15 (15 = padding, skip)
    const int cb  = 2 * (lane & 3);
    __nv_bfloat16* dh = g_wth + (size_t)q * KTOT;
    __nv_bfloat16* dl = g_wtl + (size_t)q * KTOT;

    #pragma unroll
    for (int t = 0; t < 8; ++t) {
        const int c = t * 8 + cb;
        {
            float v0 = acc[t][0], v1 = acc[t][1];
            __nv_bfloat16 h0 = __float2bfloat16(v0);
            __nv_bfloat16 h1 = __float2bfloat16(v1);
            __nv_bfloat16 l0 = __float2bfloat16(v0 - __bfloat162float(h0));
            __nv_bfloat16 l1 = __float2bfloat16(v1 - __bfloat162float(h1));
            *(__nv_bfloat162*)(dh + kp0 * 64 + c) = __nv_bfloat162(h0, h1);
            *(__nv_bfloat162*)(dl + kp0 * 64 + c) = __nv_bfloat162(l0, l1);
        }
        if (kp1 < KP) {
            float v0 = acc[t][2], v1 = acc[t][3];
            __nv_bfloat16 h0 = __float2bfloat16(v0);
            __nv_bfloat16 h1 = __float2bfloat16(v1);
            __nv_bfloat16 l0 = __float2bfloat16(v0 - __bfloat162float(h0));
            __nv_bfloat16 l1 = __float2bfloat16(v1 - __bfloat162float(h1));
            *(__nv_bfloat162*)(dh + kp1 * 64 + c) = __nv_bfloat162(h0, h1);
            *(__nv_bfloat162*)(dl + kp1 * 64 + c) = __nv_bfloat162(l0, l1);
        }
    }
}

// =============================================================================
// Kernel B: HMMA GEMM  out[128-tile][64] = weighted x W^T  (3-term bf16)
//   + fused BN partial sums (shared reduce -> 1 atomic set per CTA)
// =============================================================================
#define HB_AH(b) ((b) * 49152u + 0u)
#define HB_AL(b) ((b) * 49152u + 16384u)
#define HB_WH(b) ((b) * 49152u + 32768u)
#define HB_WL(b) ((b) * 49152u + 40960u)
#define HB_RED   98304u
#define HB_TOTAL (98304 + 512)

extern __shared__ char smH[];

static __device__ __forceinline__ void load_chunk(uint32_t sb, int buf, int qbase, int c,
                                                  int tid) {
    #pragma unroll
    for (int i = 0; i < 4; ++i) {
        const int v = i * 256 + tid;
        const int row = v >> 3, u = v & 7;
        const uint32_t d = SWZ128((uint32_t)(row * 128 + u * 16));
        const size_t so = (size_t)(qbase + row) * KTOT + c * 64 + u * 8;
        cp_async16(sb + HB_AH(buf) + d, g_wth + so);
        cp_async16(sb + HB_AL(buf) + d, g_wtl + so);
    }
    #pragma unroll
    for (int i = 0; i < 2; ++i) {
        const int v = i * 256 + tid;
        const int row = v >> 3, u = v & 7;
        const uint32_t d = SWZ128((uint32_t)(row * 128 + u * 16));
        const size_t so = (size_t)row * KTOT + c * 64 + u * 8;
        cp_async16(sb + HB_WH(buf) + d, g_Wth + so);
        cp_async16(sb + HB_WL(buf) + d, g_Wtl + so);
    }
    cp_commit();
}

__global__ void __launch_bounds__(256, 2)
kpconv_gemm_hmma(float* __restrict__ out)
{
    const uint32_t sb = smem_u32(smH);
    const int tid   = threadIdx.x;
    const int warp  = tid >> 5;
    const int lane  = tid & 31;
    const int qbase = blockIdx.x * 128;

    float* red  = (float*)(smH + HB_RED);      // [64]
    float* red2 = red + 64;                    // [64]
    if (tid < 128) red[tid] = 0.f;

    const int a_row = warp * 16 + (lane & 15);
    const int a_cb  = (lane >> 4) * 16;
    const int b_row = (lane & 7) + ((lane >> 4) << 3);
    const int b_cb  = ((lane >> 3) & 1) * 16;

    float acc[8][4];
    #pragma unroll
    for (int t = 0; t < 8; ++t)
        #pragma unroll
        for (int e = 0; e < 4; ++e) acc[t][e] = 0.f;

    load_chunk(sb, 0, qbase, 0, tid);
    load_chunk(sb, 1, qbase, 1, tid);

    #pragma unroll 1
    for (int c = 0; c < 15; ++c) {
        const int buf = c & 1;
        if (c < 14) cp_wait1(); else cp_wait0();
        __syncthreads();

        const uint32_t ahb = sb + HB_AH(buf);
        const uint32_t alb = sb + HB_AL(buf);
        const uint32_t whb = sb + HB_WH(buf);
        const uint32_t wlb = sb + HB_WL(buf);

        #pragma unroll
        for (int s = 0; s < 4; ++s) {
            const uint32_t aoff = SWZ128((uint32_t)(a_row * 128 + s * 32 + a_cb));
            uint32_t ah0, ah1, ah2, ah3, al0, al1, al2, al3;
            LDSM4(ah0, ah1, ah2, ah3, ahb + aoff);
            LDSM4(al0, al1, al2, al3, alb + aoff);

            #pragma unroll
            for (int p = 0; p < 4; ++p) {
                const uint32_t boff =
                    SWZ128((uint32_t)((p * 16 + b_row) * 128 + s * 32 + b_cb));
                uint32_t bh0, bh1, bh2, bh3, bl0, bl1, bl2, bl3;
                LDSM4(bh0, bh1, bh2, bh3, whb + boff);
                LDSM4(bl0, bl1, bl2, bl3, wlb + boff);

                MMA16816(acc[2 * p],     ah0, ah1, ah2, ah3, bh0, bh1);
                MMA16816(acc[2 * p],     ah0, ah1, ah2, ah3, bl0, bl1);
                MMA16816(acc[2 * p],     al0, al1, al2, al3, bh0, bh1);
                MMA16816(acc[2 * p + 1], ah0, ah1, ah2, ah3, bh2, bh3);
                MMA16816(acc[2 * p + 1], ah0, ah1, ah2, ah3, bl2, bl3);
                MMA16816(acc[2 * p + 1], al0, al1, al2, al3, bh2, bh3);
            }
        }

        __syncthreads();
        if (c + 2 < 15) load_chunk(sb, buf, qbase, c + 2, tid);
    }

    // ---- epilogue: write + BN partials ----
    const int tm = lane >> 2;
    const int tn = (lane & 3) * 2;
    const int n0 = qbase + warp * 16 + tm;
    #pragma unroll
    for (int t = 0; t < 8; ++t) {
        const int col = t * 8 + tn;
        *(float2*)(out + (size_t)n0 * CO + col)       = make_float2(acc[t][0], acc[t][1]);
        *(float2*)(out + (size_t)(n0 + 8) * CO + col) = make_float2(acc[t][2], acc[t][3]);
        atomicAdd(red  + col,     acc[t][0] + acc[t][2]);
        atomicAdd(red  + col + 1, acc[t][1] + acc[t][3]);
        atomicAdd(red2 + col,     fmaf(acc[t][0], acc[t][0], acc[t][2] * acc[t][2]));
        atomicAdd(red2 + col + 1, fmaf(acc[t][1], acc[t][1], acc[t][3] * acc[t][3]));
    }
    __syncthreads();
    if (tid < 64)       atomicAdd(&g_sums[tid], red[tid]);
    else if (tid < 128) atomicAdd(&g_sumsq[tid - 64], red2[tid - 64]);
}

// =============================================================================
__global__ void finalize_stats_kernel(const float* __restrict__ gamma,
                                      const float* __restrict__ beta) {
    int o = threadIdx.x;
    if (o < CO) {
        const float invN = 1.f / (float)NQ;
        float mean = g_sums[o] * invN;
        float var  = g_sumsq[o] * invN - mean * mean;
        float inv  = rsqrtf(var + 1e-5f);
        float sc   = gamma[o] * inv;
        g_scale[o] = sc;
        g_bias[o]  = fmaf(-mean, sc, beta[o]);
    }
}

__global__ void __launch_bounds__(256)
bn_act_kernel(float* __restrict__ out) {
    const int i = blockIdx.x * 256 + threadIdx.x;
    float4 v = ((const float4*)out)[i];
    const int c = (i & 15) * 4;
    float r0 = fmaf(v.x, g_scale[c + 0], g_bias[c + 0]);
    float r1 = fmaf(v.y, g_scale[c + 1], g_bias[c + 1]);
    float r2 = fmaf(v.z, g_scale[c + 2], g_bias[c + 2]);
    float r3 = fmaf(v.w, g_scale[c + 3], g_bias[c + 3]);
    r0 = (r0 >= 0.f) ? r0 : 0.1f * r0;
    r1 = (r1 >= 0.f) ? r1 : 0.1f * r1;
    r2 = (r2 >= 0.f) ? r2 : 0.1f * r2;
    r3 = (r3 >= 0.f) ? r3 : 0.1f * r3;
    ((float4*)out)[i] = make_float4(r0, r1, r2, r3);
}

// =============================================================================
extern "C" void kernel_launch(void* const* d_in, const int* in_sizes, int n_in,
                              void* d_out, int out_size) {
    const float* x      = (const float*)d_in[0];
    const float* q_pts  = (const float*)d_in[1];
    const float* s_pts  = (const float*)d_in[2];
    const int*   nbr    = (const int*)d_in[3];
    const float* kp     = (const float*)d_in[4];
    const float* Wg     = (const float*)d_in[5];
    const float* gamma  = (const float*)d_in[6];
    const float* beta   = (const float*)d_in[7];
    float*       out    = (float*)d_out;

    cudaFuncSetAttribute(kpconv_gemm_hmma,
                         cudaFuncAttributeMaxDynamicSharedMemorySize, HB_TOTAL);

    prep_x<<<(MS * CIN) / 256, 256>>>(x);
    prep_w<<<KTOT, 64>>>(Wg);
    kpconv_aggregate_tc<<<NQ / 4, 128>>>(q_pts, s_pts, nbr, kp);
    kpconv_gemm_hmma<<<NQ / 128, 256, HB_TOTAL>>>(out);
    finalize_stats_kernel<<<1, 64>>>(gamma, beta);
    bn_act_kernel<<<(NQ * CO / 4) / 256, 256>>>(out);
}